// round 2
// baseline (speedup 1.0000x reference)
#include <cuda_runtime.h>
#include <cstdint>
#include <cstddef>

// ============================================================================
// Problem constants (fixed instance)
//   LEVEL_SHAPES = [(128,128),(64,64),(32,32),(16,16)], NH=8, NL=4, NP=4, D=256
//   N=4, Lq=8192, Lin=21760, d_ff=1024
// ============================================================================
#define D_MODEL   256
#define NHEAD     8
#define NLVL      4
#define NPTS      4
#define HDIM      32          // D_MODEL / NHEAD
#define LIN_TOT   21760
#define DFF       1024

// ---------------------------------------------------------------------------
// Scratch: single static device buffer (no allocations allowed anywhere).
// Offsets in floats.
// ---------------------------------------------------------------------------
#define OFF_Q      0u                            // 32768*256  =  8388608
#define OFF_VALUE  8388608u                      // 87040*256  = 22282240
#define OFF_OFFS   30670848u                     // 32768*256  =  8388608
#define OFF_AW     39059456u                     // 32768*128  =  4194304
#define OFF_SAMP   43253760u                     // 32768*256  =  8388608
#define OFF_ATTN   51642368u                     // 32768*256  =  8388608
#define OFF_X      60030976u                     // 32768*256  =  8388608
#define OFF_H      68419584u                     // 32768*1024 = 33554432
#define OFF_FF     101974016u                    // 32768*256  =  8388608
#define SCRATCH_FLOATS 110362624u

__device__ __align__(16) float g_scratch[SCRATCH_FLOATS];

// ============================================================================
// Elementwise add: q = tgt + query_pos   (vectorized float4)
// ============================================================================
__global__ void add2_kernel(const float* __restrict__ a,
                            const float* __restrict__ b,
                            float* __restrict__ c, int n4)
{
    int i = blockIdx.x * blockDim.x + threadIdx.x;
    if (i < n4) {
        float4 va = reinterpret_cast<const float4*>(a)[i];
        float4 vb = reinterpret_cast<const float4*>(b)[i];
        float4 vc;
        vc.x = va.x + vb.x; vc.y = va.y + vb.y;
        vc.z = va.z + vb.z; vc.w = va.w + vb.w;
        reinterpret_cast<float4*>(c)[i] = vc;
    }
}

// ============================================================================
// FP32 tiled GEMM, double-buffered SMEM:
//   C[M,N] = A[M,K] @ B[K,N] + bias[N]
//   BM=BN=128, BK=8, 256 threads, 8x8 register microtile per thread.
//   One __syncthreads per K-step; next tile's global loads are prefetched
//   into registers during the FMA block.
//   Requirements (all satisfied here): M%128==0, N%128==0, K%16==0.
//   Optional: RELU epilogue; optional per-row zero mask (value padding mask).
// ============================================================================
template<bool RELU>
__launch_bounds__(256, 2)
__global__ void gemm_kernel(const float* __restrict__ A,
                            const float* __restrict__ B,
                            const float* __restrict__ bias,
                            const unsigned char* __restrict__ rowmask,
                            float* __restrict__ C,
                            int M, int N, int K)
{
    __shared__ float As[2][8][128];   // [buf][k][m] transposed A tile
    __shared__ float Bs[2][8][128];   // [buf][k][n]

    const int t  = threadIdx.x;
    const int tx = t & 15;         // 0..15  -> 8 cols each
    const int ty = t >> 4;         // 0..15  -> 8 rows each
    const int row0 = blockIdx.y * 128;
    const int col0 = blockIdx.x * 128;

    // global-load mapping
    const int ar = t >> 1;          // 0..127 (A row in tile)
    const int ac = (t & 1) * 4;     // 0 or 4 (k offset, float4)
    const int br = t >> 5;          // 0..7   (B k-row in tile)
    const int bc = (t & 31) * 4;    // 0..124 (B col, float4)

    const float* pA = &A[(size_t)(row0 + ar) * K + ac];
    const float* pB = &B[(size_t)br * N + col0 + bc];

    float acc[8][8];
#pragma unroll
    for (int i = 0; i < 8; i++)
#pragma unroll
        for (int j = 0; j < 8; j++) acc[i][j] = 0.f;

    // prologue: load tile 0 into buffer 0
    float4 av = *reinterpret_cast<const float4*>(pA);
    float4 bv = *reinterpret_cast<const float4*>(pB);
    As[0][ac + 0][ar] = av.x;
    As[0][ac + 1][ar] = av.y;
    As[0][ac + 2][ar] = av.z;
    As[0][ac + 3][ar] = av.w;
    *reinterpret_cast<float4*>(&Bs[0][br][bc]) = bv;
    __syncthreads();

    const int nTiles = K >> 3;
    int buf = 0;
    for (int tile = 0; tile < nTiles; tile++) {
        // prefetch next tile (registers) while computing current
        if (tile + 1 < nTiles) {
            av = *reinterpret_cast<const float4*>(pA + (size_t)(tile + 1) * 8);
            bv = *reinterpret_cast<const float4*>(pB + (size_t)(tile + 1) * 8 * N);
        }

#pragma unroll
        for (int kk = 0; kk < 8; kk++) {
            float4 a0 = *reinterpret_cast<const float4*>(&As[buf][kk][ty * 8]);
            float4 a1 = *reinterpret_cast<const float4*>(&As[buf][kk][ty * 8 + 4]);
            float4 b0 = *reinterpret_cast<const float4*>(&Bs[buf][kk][tx * 8]);
            float4 b1 = *reinterpret_cast<const float4*>(&Bs[buf][kk][tx * 8 + 4]);
            float ra[8] = {a0.x, a0.y, a0.z, a0.w, a1.x, a1.y, a1.z, a1.w};
            float rb[8] = {b0.x, b0.y, b0.z, b0.w, b1.x, b1.y, b1.z, b1.w};
#pragma unroll
            for (int i = 0; i < 8; i++)
#pragma unroll
                for (int j = 0; j < 8; j++)
                    acc[i][j] = fmaf(ra[i], rb[j], acc[i][j]);
        }

        if (tile + 1 < nTiles) {
            int nb = buf ^ 1;
            As[nb][ac + 0][ar] = av.x;
            As[nb][ac + 1][ar] = av.y;
            As[nb][ac + 2][ar] = av.z;
            As[nb][ac + 3][ar] = av.w;
            *reinterpret_cast<float4*>(&Bs[nb][br][bc]) = bv;
            __syncthreads();
            buf = nb;
        }
    }

#pragma unroll
    for (int i = 0; i < 8; i++) {
        int row = row0 + ty * 8 + i;
        bool zero = (rowmask != nullptr) && (rowmask[row] != 0);
#pragma unroll
        for (int j = 0; j < 8; j += 4) {
            int col = col0 + tx * 8 + j;
            float4 v;
            v.x = acc[i][j + 0] + bias[col + 0];
            v.y = acc[i][j + 1] + bias[col + 1];
            v.z = acc[i][j + 2] + bias[col + 2];
            v.w = acc[i][j + 3] + bias[col + 3];
            if (RELU) {
                v.x = fmaxf(v.x, 0.f); v.y = fmaxf(v.y, 0.f);
                v.z = fmaxf(v.z, 0.f); v.w = fmaxf(v.w, 0.f);
            }
            if (zero) { v.x = 0.f; v.y = 0.f; v.z = 0.f; v.w = 0.f; }
            *reinterpret_cast<float4*>(&C[(size_t)row * N + col]) = v;
        }
    }
}

// ============================================================================
// Deformable sampling: one block (256 threads) per query.
//   - threads 0..127: softmax over 16 (per head) + sampling-location compute
//   - all 256 threads: thread t = (head = t>>5, d = t&31); bilinear gather over
//     4 levels x 4 points, accumulate weighted sum -> out[q][head*32+d]
// Value layout: [N, Lin, 256] row-major; channel = head*32 + d.
// ============================================================================
__global__ void sample_kernel(const float* __restrict__ g_off,
                              const float* __restrict__ g_aw,
                              const float* __restrict__ g_value,
                              const float* __restrict__ refpts,
                              float* __restrict__ g_out,
                              int Lq, int Lin)
{
    const int q = blockIdx.x;            // global query row (n*Lq + lq)
    const int n = q / Lq;
    const int t = threadIdx.x;

    __shared__ float s_locx[128];
    __shared__ float s_locy[128];
    __shared__ float s_w[128];

    if (t < 128) {
        // t = h*16 + l*4 + p
        const int l = (t >> 2) & 3;
        // softmax over groups of 16 (aligned within warp)
        float a = g_aw[(size_t)q * 128 + t];
        float m = a;
#pragma unroll
        for (int o = 8; o > 0; o >>= 1)
            m = fmaxf(m, __shfl_xor_sync(0xffffffffu, m, o));
        float e = expf(a - m);
        float s = e;
#pragma unroll
        for (int o = 8; o > 0; o >>= 1)
            s += __shfl_xor_sync(0xffffffffu, s, o);
        s_w[t] = e / s;

        // sampling location: ref + off / [W_l, H_l]
        const float invWH[4] = {1.f / 128.f, 1.f / 64.f, 1.f / 32.f, 1.f / 16.f};
        float ox = g_off[(size_t)q * 256 + 2 * t + 0];
        float oy = g_off[(size_t)q * 256 + 2 * t + 1];
        float rx = refpts[((size_t)q * 4 + l) * 2 + 0];
        float ry = refpts[((size_t)q * 4 + l) * 2 + 1];
        s_locx[t] = rx + ox * invWH[l];
        s_locy[t] = ry + oy * invWH[l];
    }
    __syncthreads();

    const int h = t >> 5;
    const int d = t & 31;

    const int HW[4] = {128, 64, 32, 16};   // square levels
    const int ST[4] = {0, 16384, 20480, 21504};

    float acc = 0.f;
#pragma unroll
    for (int l = 0; l < NLVL; l++) {
        const int   W  = HW[l];
        const float Wf = (float)W;
        const float* vbase =
            g_value + ((size_t)n * Lin + ST[l]) * D_MODEL + h * HDIM + d;
#pragma unroll
        for (int p = 0; p < NPTS; p++) {
            const int pi = h * 16 + l * 4 + p;
            const float w = s_w[pi];
            const float x = s_locx[pi] * Wf - 0.5f;
            const float y = s_locy[pi] * Wf - 0.5f;   // H == W per level
            const float x0 = floorf(x), y0 = floorf(y);
            const float dx = x - x0,   dy = y - y0;
            const float wx[2] = {1.f - dx, dx};
            const float wy[2] = {1.f - dy, dy};
            float samp = 0.f;
#pragma unroll
            for (int cy = 0; cy < 2; cy++) {
#pragma unroll
                for (int cx = 0; cx < 2; cx++) {
                    float fx = x0 + (float)cx;
                    float fy = y0 + (float)cy;
                    if (fx >= 0.f && fx <= Wf - 1.f &&
                        fy >= 0.f && fy <= Wf - 1.f) {
                        int ix = (int)fx;
                        int iy = (int)fy;
                        samp += wx[cx] * wy[cy] *
                                __ldg(&vbase[(size_t)(iy * W + ix) * D_MODEL]);
                    }
                }
            }
            acc += w * samp;
        }
    }
    g_out[(size_t)q * D_MODEL + t] = acc;
}

// ============================================================================
// Fused residual-add + LayerNorm over last dim (256). One warp per row,
// 8 elements per lane.
// ============================================================================
__global__ void add_ln_kernel(const float* __restrict__ a,
                              const float* __restrict__ b,
                              const float* __restrict__ gamma,
                              const float* __restrict__ beta,
                              float* __restrict__ out, int rows)
{
    const int row  = blockIdx.x * blockDim.y + threadIdx.y;
    if (row >= rows) return;
    const int lane = threadIdx.x;

    const float* pa = a + (size_t)row * D_MODEL;
    const float* pb = b + (size_t)row * D_MODEL;

    float v[8];
    float s = 0.f, s2 = 0.f;
#pragma unroll
    for (int i = 0; i < 8; i++) {
        int c = lane + 32 * i;
        float x = pa[c] + pb[c];
        v[i] = x;
        s  += x;
        s2 += x * x;
    }
#pragma unroll
    for (int o = 16; o > 0; o >>= 1) {
        s  += __shfl_xor_sync(0xffffffffu, s,  o);
        s2 += __shfl_xor_sync(0xffffffffu, s2, o);
    }
    const float mean = s * (1.f / 256.f);
    const float var  = s2 * (1.f / 256.f) - mean * mean;
    const float inv  = rsqrtf(var + 1e-5f);

    float* po = out + (size_t)row * D_MODEL;
#pragma unroll
    for (int i = 0; i < 8; i++) {
        int c = lane + 32 * i;
        po[c] = (v[i] - mean) * inv * gamma[c] + beta[c];
    }
}

// ============================================================================
// Launch
// ============================================================================
extern "C" void kernel_launch(void* const* d_in, const int* in_sizes, int n_in,
                              void* d_out, int out_size)
{
    const float* tgt    = (const float*)d_in[0];
    const float* qpos   = (const float*)d_in[1];
    const float* refpts = (const float*)d_in[2];
    const float* src    = (const float*)d_in[3];
    // d_in[4] = src_spatial_shapes (int64), d_in[5] = level_start_index (int64)
    //   -> compile-time constants for this fixed problem instance.
    const unsigned char* mask = (const unsigned char*)d_in[6];
    const float* W_off  = (const float*)d_in[7];
    const float* b_off  = (const float*)d_in[8];
    const float* W_attn = (const float*)d_in[9];
    const float* b_attn = (const float*)d_in[10];
    const float* W_val  = (const float*)d_in[11];
    const float* b_val  = (const float*)d_in[12];
    const float* W_out  = (const float*)d_in[13];
    const float* b_out  = (const float*)d_in[14];
    const float* ln1_g  = (const float*)d_in[15];
    const float* ln1_b  = (const float*)d_in[16];
    const float* W_fc1  = (const float*)d_in[17];
    const float* b_fc1  = (const float*)d_in[18];
    const float* W_fc2  = (const float*)d_in[19];
    const float* b_fc2  = (const float*)d_in[20];
    const float* ln2_g  = (const float*)d_in[21];
    const float* ln2_b  = (const float*)d_in[22];
    float* out = (float*)d_out;

    const int NLq  = in_sizes[0] / D_MODEL;   // N * Lq  (32768)
    const int NLin = in_sizes[3] / D_MODEL;   // N * Lin (87040)
    const int Nb   = NLin / LIN_TOT;          // batch N (4)
    const int Lq   = NLq / Nb;                // 8192

    void* sp = nullptr;
    cudaGetSymbolAddress(&sp, g_scratch);
    float* S       = (float*)sp;
    float* g_q     = S + OFF_Q;
    float* g_value = S + OFF_VALUE;
    float* g_offs  = S + OFF_OFFS;
    float* g_aw    = S + OFF_AW;
    float* g_samp  = S + OFF_SAMP;
    float* g_attn  = S + OFF_ATTN;
    float* g_x     = S + OFF_X;
    float* g_h     = S + OFF_H;
    float* g_ff    = S + OFF_FF;

    // 1. q = tgt + query_pos
    {
        int n4 = (NLq * D_MODEL) / 4;
        add2_kernel<<<(n4 + 255) / 256, 256>>>(tgt, qpos, g_q, n4);
    }

    // 2. value = src @ W_val + b_val, masked rows zeroed
    gemm_kernel<false><<<dim3(D_MODEL / 128, NLin / 128), 256>>>(
        src, W_val, b_val, mask, g_value, NLin, D_MODEL, D_MODEL);

    // 3. sampling offsets: q @ W_off + b_off     [NLq, 256]
    gemm_kernel<false><<<dim3(D_MODEL / 128, NLq / 128), 256>>>(
        g_q, W_off, b_off, nullptr, g_offs, NLq, D_MODEL, D_MODEL);

    // 4. attention logits: q @ W_attn + b_attn   [NLq, 128]
    gemm_kernel<false><<<dim3(128 / 128, NLq / 128), 256>>>(
        g_q, W_attn, b_attn, nullptr, g_aw, NLq, 128, D_MODEL);

    // 5. softmax + deformable bilinear sampling -> g_samp [NLq, 256]
    sample_kernel<<<NLq, 256>>>(g_offs, g_aw, g_value, refpts, g_samp, Lq, LIN_TOT);

    // 6. attn_out = samp @ W_out + b_out
    gemm_kernel<false><<<dim3(D_MODEL / 128, NLq / 128), 256>>>(
        g_samp, W_out, b_out, nullptr, g_attn, NLq, D_MODEL, D_MODEL);

    // 7. x = LN(tgt + attn_out)
    add_ln_kernel<<<NLq / 8, dim3(32, 8)>>>(tgt, g_attn, ln1_g, ln1_b, g_x, NLq);

    // 8. h = relu(x @ W_fc1 + b_fc1)             [NLq, 1024]
    gemm_kernel<true><<<dim3(DFF / 128, NLq / 128), 256>>>(
        g_x, W_fc1, b_fc1, nullptr, g_h, NLq, DFF, D_MODEL);

    // 9. ff = h @ W_fc2 + b_fc2                  [NLq, 256]
    gemm_kernel<false><<<dim3(D_MODEL / 128, NLq / 128), 256>>>(
        g_h, W_fc2, b_fc2, nullptr, g_ff, NLq, D_MODEL, DFF);

    // 10. out = LN(x + ff)
    add_ln_kernel<<<NLq / 8, dim3(32, 8)>>>(g_x, g_ff, ln2_g, ln2_b, out, NLq);
}

// round 3
// speedup vs baseline: 1.1302x; 1.1302x over previous
#include <cuda_runtime.h>
#include <cstdint>
#include <cstddef>

// ============================================================================
// Problem constants (fixed instance)
//   LEVEL_SHAPES = [(128,128),(64,64),(32,32),(16,16)], NH=8, NL=4, NP=4, D=256
//   N=4, Lq=8192, Lin=21760, d_ff=1024
// ============================================================================
#define D_MODEL   256
#define NHEAD     8
#define NLVL      4
#define NPTS      4
#define HDIM      32
#define LIN_TOT   21760
#define DFF       1024

// ---------------------------------------------------------------------------
// Scratch offsets (floats)
// ---------------------------------------------------------------------------
#define OFF_Q      0u                            // 32768*256  =  8388608
#define OFF_VALUE  8388608u                      // 87040*256  = 22282240
#define OFF_OA     30670848u                     // 32768*384  = 12582912 (offs|aw)
#define OFF_SAMP   43253760u                     // 32768*256  =  8388608
#define OFF_ATTN   51642368u                     // 32768*256  =  8388608
#define OFF_X      60030976u                     // 32768*256  =  8388608
#define OFF_H      68419584u                     // 32768*1024 = 33554432
#define OFF_FF     101974016u                    // 32768*256  =  8388608
#define OFF_WCAT   110362624u                    // 256*384    =    98304
#define OFF_BCAT   110460928u                    // 384
#define SCRATCH_FLOATS 110461312u

__device__ __align__(16) float g_scratch[SCRATCH_FLOATS];

// ---------------------------------------------------------------------------
// Packed f32x2 helpers (sm_103a): one issue slot = 2 fp32 FMAs, bit-exact.
// ---------------------------------------------------------------------------
__device__ __forceinline__ void ffma2(unsigned long long& d,
                                      unsigned long long a,
                                      unsigned long long b)
{
    asm("fma.rn.f32x2 %0, %1, %2, %0;" : "+l"(d) : "l"(a), "l"(b));
}
__device__ __forceinline__ unsigned long long dup2(float x)
{
    unsigned long long r;
    asm("mov.b64 %0, {%1, %1};" : "=l"(r) : "f"(x));
    return r;
}
__device__ __forceinline__ void unpack2(unsigned long long v, float& lo, float& hi)
{
    unsigned a, b;
    asm("mov.b64 {%0, %1}, %2;" : "=r"(a), "=r"(b) : "l"(v));
    lo = __uint_as_float(a);
    hi = __uint_as_float(b);
}

// ============================================================================
// q = tgt + query_pos   (float4)
// ============================================================================
__global__ void add2_kernel(const float* __restrict__ a,
                            const float* __restrict__ b,
                            float* __restrict__ c, int n4)
{
    int i = blockIdx.x * blockDim.x + threadIdx.x;
    if (i < n4) {
        float4 va = reinterpret_cast<const float4*>(a)[i];
        float4 vb = reinterpret_cast<const float4*>(b)[i];
        float4 vc;
        vc.x = va.x + vb.x; vc.y = va.y + vb.y;
        vc.z = va.z + vb.z; vc.w = va.w + vb.w;
        reinterpret_cast<float4*>(c)[i] = vc;
    }
}

// ============================================================================
// Concat [W_off | W_attn] -> Wc[256][384], [b_off | b_attn] -> bc[384]
// ============================================================================
__global__ void concat_w_kernel(const float* __restrict__ Woff,
                                const float* __restrict__ boff,
                                const float* __restrict__ Wattn,
                                const float* __restrict__ battn,
                                float* __restrict__ Wc,
                                float* __restrict__ bc)
{
    int i = blockIdx.x * blockDim.x + threadIdx.x;
    if (i < 256 * 384) {
        int k = i / 384, c = i % 384;
        Wc[i] = (c < 256) ? Woff[k * 256 + c] : Wattn[k * 128 + (c - 256)];
    }
    if (i < 384) bc[i] = (i < 256) ? boff[i] : battn[i - 256];
}

// ============================================================================
// FP32 tiled GEMM, double-buffered SMEM, packed-FFMA2 mainloop:
//   C[M,N] = A[M,K] @ B[K,N] + bias[N]
//   BM=BN=128, BK=8, 256 threads, 8x8 microtile held as 8x4 f32x2 pairs.
//   Requirements: M%128==0, N%128==0, K%8==0.
// ============================================================================
template<bool RELU>
__launch_bounds__(256, 2)
__global__ void gemm_kernel(const float* __restrict__ A,
                            const float* __restrict__ B,
                            const float* __restrict__ bias,
                            const unsigned char* __restrict__ rowmask,
                            float* __restrict__ C,
                            int M, int N, int K)
{
    __shared__ float As[2][8][128];   // [buf][k][m]
    __shared__ float Bs[2][8][128];   // [buf][k][n]

    const int t  = threadIdx.x;
    const int tx = t & 15;
    const int ty = t >> 4;
    const int row0 = blockIdx.y * 128;
    const int col0 = blockIdx.x * 128;

    const int ar = t >> 1;
    const int ac = (t & 1) * 4;
    const int br = t >> 5;
    const int bc = (t & 31) * 4;

    const float* pA = &A[(size_t)(row0 + ar) * K + ac];
    const float* pB = &B[(size_t)br * N + col0 + bc];

    unsigned long long acc2[8][4];
#pragma unroll
    for (int i = 0; i < 8; i++)
#pragma unroll
        for (int j = 0; j < 4; j++) acc2[i][j] = 0ull;

    float4 av = *reinterpret_cast<const float4*>(pA);
    float4 bv = *reinterpret_cast<const float4*>(pB);
    As[0][ac + 0][ar] = av.x;
    As[0][ac + 1][ar] = av.y;
    As[0][ac + 2][ar] = av.z;
    As[0][ac + 3][ar] = av.w;
    *reinterpret_cast<float4*>(&Bs[0][br][bc]) = bv;
    __syncthreads();

    const int nTiles = K >> 3;
    int buf = 0;
    for (int tile = 0; tile < nTiles; tile++) {
        if (tile + 1 < nTiles) {
            av = *reinterpret_cast<const float4*>(pA + (size_t)(tile + 1) * 8);
            bv = *reinterpret_cast<const float4*>(pB + (size_t)(tile + 1) * 8 * N);
        }

#pragma unroll
        for (int kk = 0; kk < 8; kk++) {
            float4 a0 = *reinterpret_cast<const float4*>(&As[buf][kk][ty * 8]);
            float4 a1 = *reinterpret_cast<const float4*>(&As[buf][kk][ty * 8 + 4]);
            ulonglong2 p0 = *reinterpret_cast<const ulonglong2*>(&Bs[buf][kk][tx * 8]);
            ulonglong2 p1 = *reinterpret_cast<const ulonglong2*>(&Bs[buf][kk][tx * 8 + 4]);
            unsigned long long b2[4] = {p0.x, p0.y, p1.x, p1.y};
            float ra[8] = {a0.x, a0.y, a0.z, a0.w, a1.x, a1.y, a1.z, a1.w};
#pragma unroll
            for (int i = 0; i < 8; i++) {
                unsigned long long aa = dup2(ra[i]);
#pragma unroll
                for (int jp = 0; jp < 4; jp++)
                    ffma2(acc2[i][jp], aa, b2[jp]);
            }
        }

        if (tile + 1 < nTiles) {
            int nb = buf ^ 1;
            As[nb][ac + 0][ar] = av.x;
            As[nb][ac + 1][ar] = av.y;
            As[nb][ac + 2][ar] = av.z;
            As[nb][ac + 3][ar] = av.w;
            *reinterpret_cast<float4*>(&Bs[nb][br][bc]) = bv;
            __syncthreads();
            buf = nb;
        }
    }

#pragma unroll
    for (int i = 0; i < 8; i++) {
        int row = row0 + ty * 8 + i;
        bool zero = (rowmask != nullptr) && (rowmask[row] != 0);
        float vals[8];
#pragma unroll
        for (int jp = 0; jp < 4; jp++)
            unpack2(acc2[i][jp], vals[2 * jp], vals[2 * jp + 1]);
#pragma unroll
        for (int j = 0; j < 8; j += 4) {
            int col = col0 + tx * 8 + j;
            float4 v;
            v.x = vals[j + 0] + bias[col + 0];
            v.y = vals[j + 1] + bias[col + 1];
            v.z = vals[j + 2] + bias[col + 2];
            v.w = vals[j + 3] + bias[col + 3];
            if (RELU) {
                v.x = fmaxf(v.x, 0.f); v.y = fmaxf(v.y, 0.f);
                v.z = fmaxf(v.z, 0.f); v.w = fmaxf(v.w, 0.f);
            }
            if (zero) { v.x = 0.f; v.y = 0.f; v.z = 0.f; v.w = 0.f; }
            *reinterpret_cast<float4*>(&C[(size_t)row * N + col]) = v;
        }
    }
}

// ============================================================================
// Deformable sampling: one block (256 threads) per query.
// Reads fused projection buffer g_oa: row = [offs(256) | aw(128)], stride 384.
// ============================================================================
__global__ void sample_kernel(const float* __restrict__ g_oa,
                              const float* __restrict__ g_value,
                              const float* __restrict__ refpts,
                              float* __restrict__ g_out,
                              int Lq, int Lin)
{
    const int q = blockIdx.x;
    const int n = q / Lq;
    const int t = threadIdx.x;

    __shared__ float s_locx[128];
    __shared__ float s_locy[128];
    __shared__ float s_w[128];

    if (t < 128) {
        const int l = (t >> 2) & 3;
        float a = g_oa[(size_t)q * 384 + 256 + t];
        float m = a;
#pragma unroll
        for (int o = 8; o > 0; o >>= 1)
            m = fmaxf(m, __shfl_xor_sync(0xffffffffu, m, o));
        float e = expf(a - m);
        float s = e;
#pragma unroll
        for (int o = 8; o > 0; o >>= 1)
            s += __shfl_xor_sync(0xffffffffu, s, o);
        s_w[t] = e / s;

        const float invWH[4] = {1.f / 128.f, 1.f / 64.f, 1.f / 32.f, 1.f / 16.f};
        float ox = g_oa[(size_t)q * 384 + 2 * t + 0];
        float oy = g_oa[(size_t)q * 384 + 2 * t + 1];
        float rx = refpts[((size_t)q * 4 + l) * 2 + 0];
        float ry = refpts[((size_t)q * 4 + l) * 2 + 1];
        s_locx[t] = rx + ox * invWH[l];
        s_locy[t] = ry + oy * invWH[l];
    }
    __syncthreads();

    const int h = t >> 5;
    const int d = t & 31;

    const int HW[4] = {128, 64, 32, 16};
    const int ST[4] = {0, 16384, 20480, 21504};

    float acc = 0.f;
#pragma unroll
    for (int l = 0; l < NLVL; l++) {
        const int   W  = HW[l];
        const float Wf = (float)W;
        const float* vbase =
            g_value + ((size_t)n * Lin + ST[l]) * D_MODEL + h * HDIM + d;
#pragma unroll
        for (int p = 0; p < NPTS; p++) {
            const int pi = h * 16 + l * 4 + p;
            const float w = s_w[pi];
            const float x = s_locx[pi] * Wf - 0.5f;
            const float y = s_locy[pi] * Wf - 0.5f;
            const float x0 = floorf(x), y0 = floorf(y);
            const float dx = x - x0,   dy = y - y0;
            const float wx[2] = {1.f - dx, dx};
            const float wy[2] = {1.f - dy, dy};
            float samp = 0.f;
#pragma unroll
            for (int cy = 0; cy < 2; cy++) {
#pragma unroll
                for (int cx = 0; cx < 2; cx++) {
                    float fx = x0 + (float)cx;
                    float fy = y0 + (float)cy;
                    if (fx >= 0.f && fx <= Wf - 1.f &&
                        fy >= 0.f && fy <= Wf - 1.f) {
                        int ix = (int)fx;
                        int iy = (int)fy;
                        samp += wx[cx] * wy[cy] *
                                __ldg(&vbase[(size_t)(iy * W + ix) * D_MODEL]);
                    }
                }
            }
            acc += w * samp;
        }
    }
    g_out[(size_t)q * D_MODEL + t] = acc;
}

// ============================================================================
// Fused residual-add + LayerNorm over last dim (256). One warp per row.
// ============================================================================
__global__ void add_ln_kernel(const float* __restrict__ a,
                              const float* __restrict__ b,
                              const float* __restrict__ gamma,
                              const float* __restrict__ beta,
                              float* __restrict__ out, int rows)
{
    const int row  = blockIdx.x * blockDim.y + threadIdx.y;
    if (row >= rows) return;
    const int lane = threadIdx.x;

    const float* pa = a + (size_t)row * D_MODEL;
    const float* pb = b + (size_t)row * D_MODEL;

    float v[8];
    float s = 0.f, s2 = 0.f;
#pragma unroll
    for (int i = 0; i < 8; i++) {
        int c = lane + 32 * i;
        float x = pa[c] + pb[c];
        v[i] = x;
        s  += x;
        s2 += x * x;
    }
#pragma unroll
    for (int o = 16; o > 0; o >>= 1) {
        s  += __shfl_xor_sync(0xffffffffu, s,  o);
        s2 += __shfl_xor_sync(0xffffffffu, s2, o);
    }
    const float mean = s * (1.f / 256.f);
    const float var  = s2 * (1.f / 256.f) - mean * mean;
    const float inv  = rsqrtf(var + 1e-5f);

    float* po = out + (size_t)row * D_MODEL;
#pragma unroll
    for (int i = 0; i < 8; i++) {
        int c = lane + 32 * i;
        po[c] = (v[i] - mean) * inv * gamma[c] + beta[c];
    }
}

// ============================================================================
// Launch
// ============================================================================
extern "C" void kernel_launch(void* const* d_in, const int* in_sizes, int n_in,
                              void* d_out, int out_size)
{
    const float* tgt    = (const float*)d_in[0];
    const float* qpos   = (const float*)d_in[1];
    const float* refpts = (const float*)d_in[2];
    const float* src    = (const float*)d_in[3];
    const unsigned char* mask = (const unsigned char*)d_in[6];
    const float* W_off  = (const float*)d_in[7];
    const float* b_off  = (const float*)d_in[8];
    const float* W_attn = (const float*)d_in[9];
    const float* b_attn = (const float*)d_in[10];
    const float* W_val  = (const float*)d_in[11];
    const float* b_val  = (const float*)d_in[12];
    const float* W_out  = (const float*)d_in[13];
    const float* b_out  = (const float*)d_in[14];
    const float* ln1_g  = (const float*)d_in[15];
    const float* ln1_b  = (const float*)d_in[16];
    const float* W_fc1  = (const float*)d_in[17];
    const float* b_fc1  = (const float*)d_in[18];
    const float* W_fc2  = (const float*)d_in[19];
    const float* b_fc2  = (const float*)d_in[20];
    const float* ln2_g  = (const float*)d_in[21];
    const float* ln2_b  = (const float*)d_in[22];
    float* out = (float*)d_out;

    const int NLq  = in_sizes[0] / D_MODEL;   // 32768
    const int NLin = in_sizes[3] / D_MODEL;   // 87040
    const int Nb   = NLin / LIN_TOT;          // 4
    const int Lq   = NLq / Nb;                // 8192

    void* sp = nullptr;
    cudaGetSymbolAddress(&sp, g_scratch);
    float* S       = (float*)sp;
    float* g_q     = S + OFF_Q;
    float* g_value = S + OFF_VALUE;
    float* g_oa    = S + OFF_OA;
    float* g_samp  = S + OFF_SAMP;
    float* g_attn  = S + OFF_ATTN;
    float* g_x     = S + OFF_X;
    float* g_h     = S + OFF_H;
    float* g_ff    = S + OFF_FF;
    float* g_Wc    = S + OFF_WCAT;
    float* g_bc    = S + OFF_BCAT;

    // 0. concat [W_off|W_attn] weights (tiny)
    concat_w_kernel<<<(256 * 384 + 255) / 256, 256>>>(
        W_off, b_off, W_attn, b_attn, g_Wc, g_bc);

    // 1. q = tgt + query_pos
    {
        int n4 = (NLq * D_MODEL) / 4;
        add2_kernel<<<(n4 + 255) / 256, 256>>>(tgt, qpos, g_q, n4);
    }

    // 2. value = src @ W_val + b_val, masked rows zeroed
    gemm_kernel<false><<<dim3(D_MODEL / 128, NLin / 128), 256>>>(
        src, W_val, b_val, mask, g_value, NLin, D_MODEL, D_MODEL);

    // 3. fused offsets+logits: q @ [W_off|W_attn]  -> [NLq, 384]
    gemm_kernel<false><<<dim3(384 / 128, NLq / 128), 256>>>(
        g_q, g_Wc, g_bc, nullptr, g_oa, NLq, 384, D_MODEL);

    // 4. softmax + deformable bilinear sampling -> g_samp [NLq, 256]
    sample_kernel<<<NLq, 256>>>(g_oa, g_value, refpts, g_samp, Lq, LIN_TOT);

    // 5. attn_out = samp @ W_out + b_out
    gemm_kernel<false><<<dim3(D_MODEL / 128, NLq / 128), 256>>>(
        g_samp, W_out, b_out, nullptr, g_attn, NLq, D_MODEL, D_MODEL);

    // 6. x = LN(tgt + attn_out)
    add_ln_kernel<<<NLq / 8, dim3(32, 8)>>>(tgt, g_attn, ln1_g, ln1_b, g_x, NLq);

    // 7. h = relu(x @ W_fc1 + b_fc1)
    gemm_kernel<true><<<dim3(DFF / 128, NLq / 128), 256>>>(
        g_x, W_fc1, b_fc1, nullptr, g_h, NLq, DFF, D_MODEL);

    // 8. ff = h @ W_fc2 + b_fc2
    gemm_kernel<false><<<dim3(D_MODEL / 128, NLq / 128), 256>>>(
        g_h, W_fc2, b_fc2, nullptr, g_ff, NLq, D_MODEL, DFF);

    // 9. out = LN(x + ff)
    add_ln_kernel<<<NLq / 8, dim3(32, 8)>>>(g_x, g_ff, ln2_g, ln2_b, out, NLq);
}

// round 11
// speedup vs baseline: 1.9556x; 1.7302x over previous
#include <cuda_runtime.h>
#include <cstdint>
#include <cstddef>

// ============================================================================
// Problem constants (fixed instance)
// ============================================================================
#define D_MODEL   256
#define NHEAD     8
#define NLVL      4
#define NPTS      4
#define HDIM      32
#define LIN_TOT   21760
#define DFF       1024

// ---------------------------------------------------------------------------
// Scratch offsets (floats)
// ---------------------------------------------------------------------------
#define OFF_VALUE  8388608u
#define OFF_OA     30670848u
#define OFF_SAMP   43253760u
#define OFF_ATTN   51642368u
#define OFF_X      60030976u
#define OFF_H      68419584u
#define OFF_FF     101974016u
#define OFF_WCAT   110362624u
#define OFF_BCAT   110460928u
#define SCRATCH_FLOATS 110461312u

__device__ __align__(16) float g_scratch[SCRATCH_FLOATS];

// ============================================================================
// Concat [W_off | W_attn] -> Wc[256][384], [b_off | b_attn] -> bc[384]
// ============================================================================
__global__ void concat_w_kernel(const float* __restrict__ Woff,
                                const float* __restrict__ boff,
                                const float* __restrict__ Wattn,
                                const float* __restrict__ battn,
                                float* __restrict__ Wc,
                                float* __restrict__ bc)
{
    int i = blockIdx.x * blockDim.x + threadIdx.x;
    if (i < 256 * 384) {
        int k = i / 384, c = i % 384;
        Wc[i] = (c < 256) ? Woff[k * 256 + c] : Wattn[k * 128 + (c - 256)];
    }
    if (i < 384) bc[i] = (i < 256) ? boff[i] : battn[i - 256];
}

// ============================================================================
// TF32 tensor-core GEMM:  C[M,N] = (A [+ A2]) @ B + bias[N]
//   mma.sync.aligned.m16n8k8.row.col.f32.tf32.tf32.f32
//   Block tile 128x128, K-tile 16, 256 threads = 8 warps as 4(m) x 2(n).
//   Warp tile 32x64 -> 2 m-tiles x 8 n-tiles of m16n8.
//   SMEM: A as [m][k] pad 20, B as [k][n] pad 136 (conflict-free for the
//   m16n8k8 fragment lane patterns). Double-buffered, register prefetch.
//   Inputs rounded to tf32 (cvt.rna) on the SMEM-store path.
//   A2 (optional): elementwise residual added to A before conversion.
//   rowmask (optional): zero out masked C rows.
//   Requirements: M%128==0, N%128==0, K%16==0.
// ============================================================================
#define PAD_A 20
#define PAD_B 136

__device__ __forceinline__ uint32_t f2tf32(float f)
{
    uint32_t u;
    asm("cvt.rna.tf32.f32 %0, %1;" : "=r"(u) : "f"(f));
    return u;
}

__device__ __forceinline__ void mma_tf32(float c[4], const uint32_t a[4],
                                         const uint32_t b[2])
{
    asm volatile(
        "mma.sync.aligned.m16n8k8.row.col.f32.tf32.tf32.f32 "
        "{%0,%1,%2,%3}, {%4,%5,%6,%7}, {%8,%9}, {%0,%1,%2,%3};"
        : "+f"(c[0]), "+f"(c[1]), "+f"(c[2]), "+f"(c[3])
        : "r"(a[0]), "r"(a[1]), "r"(a[2]), "r"(a[3]),
          "r"(b[0]), "r"(b[1]));
}

template<bool RELU>
__launch_bounds__(256, 2)
__global__ void gemm_tf32_kernel(const float* __restrict__ A,
                                 const float* __restrict__ A2,
                                 const float* __restrict__ B,
                                 const float* __restrict__ bias,
                                 const unsigned char* __restrict__ rowmask,
                                 float* __restrict__ C,
                                 int M, int N, int K)
{
    __shared__ uint32_t As[2][128 * PAD_A];   // [m][k], tf32 bits
    __shared__ uint32_t Bs[2][16 * PAD_B];    // [k][n], tf32 bits

    const int t    = threadIdx.x;
    const int lane = t & 31;
    const int wid  = t >> 5;
    const int gid  = lane >> 2;      // 0..7
    const int qid  = lane & 3;       // 0..3
    const int wm   = wid >> 1;       // 0..3 -> m offset wm*32
    const int wn   = wid & 1;        // 0..1 -> n offset wn*64
    const int row0 = blockIdx.y * 128;
    const int col0 = blockIdx.x * 128;

    const int a_r  = t >> 1;             // 0..127
    const int a_k  = (t & 1) * 8;        // 0 or 8
    const int b_k  = t >> 4;             // 0..15
    const int b_c  = (t & 15) * 8;       // 0..120

    const size_t aoff = (size_t)(row0 + a_r) * K + a_k;
    const float* pA  = A + aoff;
    const float* pA2 = (A2 != nullptr) ? (A2 + aoff) : nullptr;
    const float* pB  = &B[(size_t)b_k * N + col0 + b_c];

    float acc[2][8][4];
#pragma unroll
    for (int mt = 0; mt < 2; mt++)
#pragma unroll
        for (int nt = 0; nt < 8; nt++)
#pragma unroll
            for (int i = 0; i < 4; i++) acc[mt][nt][i] = 0.f;

    // ---- prologue: stage tile 0 ----
    float4 av0 = *reinterpret_cast<const float4*>(pA);
    float4 av1 = *reinterpret_cast<const float4*>(pA + 4);
    float4 bv0 = *reinterpret_cast<const float4*>(pB);
    float4 bv1 = *reinterpret_cast<const float4*>(pB + 4);
    if (pA2 != nullptr) {
        float4 r0 = *reinterpret_cast<const float4*>(pA2);
        float4 r1 = *reinterpret_cast<const float4*>(pA2 + 4);
        av0.x += r0.x; av0.y += r0.y; av0.z += r0.z; av0.w += r0.w;
        av1.x += r1.x; av1.y += r1.y; av1.z += r1.z; av1.w += r1.w;
    }
    {
        uint32_t* as = &As[0][a_r * PAD_A + a_k];
        as[0] = f2tf32(av0.x); as[1] = f2tf32(av0.y);
        as[2] = f2tf32(av0.z); as[3] = f2tf32(av0.w);
        as[4] = f2tf32(av1.x); as[5] = f2tf32(av1.y);
        as[6] = f2tf32(av1.z); as[7] = f2tf32(av1.w);
        uint32_t* bs = &Bs[0][b_k * PAD_B + b_c];
        bs[0] = f2tf32(bv0.x); bs[1] = f2tf32(bv0.y);
        bs[2] = f2tf32(bv0.z); bs[3] = f2tf32(bv0.w);
        bs[4] = f2tf32(bv1.x); bs[5] = f2tf32(bv1.y);
        bs[6] = f2tf32(bv1.z); bs[7] = f2tf32(bv1.w);
    }
    __syncthreads();

    const int nTiles = K >> 4;
    int buf = 0;
    for (int tile = 0; tile < nTiles; tile++) {
        if (tile + 1 < nTiles) {
            const float* nA = pA + (size_t)(tile + 1) * 16;
            const float* nB = pB + (size_t)(tile + 1) * 16 * N;
            av0 = *reinterpret_cast<const float4*>(nA);
            av1 = *reinterpret_cast<const float4*>(nA + 4);
            bv0 = *reinterpret_cast<const float4*>(nB);
            bv1 = *reinterpret_cast<const float4*>(nB + 4);
            if (pA2 != nullptr) {
                const float* nA2 = pA2 + (size_t)(tile + 1) * 16;
                float4 r0 = *reinterpret_cast<const float4*>(nA2);
                float4 r1 = *reinterpret_cast<const float4*>(nA2 + 4);
                av0.x += r0.x; av0.y += r0.y; av0.z += r0.z; av0.w += r0.w;
                av1.x += r1.x; av1.y += r1.y; av1.z += r1.z; av1.w += r1.w;
            }
        }

#pragma unroll
        for (int kk = 0; kk < 2; kk++) {
            const int k8 = kk * 8;
            uint32_t afr[2][4];
#pragma unroll
            for (int mt = 0; mt < 2; mt++) {
                int m = wm * 32 + mt * 16;
                const uint32_t* ab = &As[buf][0];
                afr[mt][0] = ab[(m + gid)     * PAD_A + k8 + qid];
                afr[mt][1] = ab[(m + 8 + gid) * PAD_A + k8 + qid];
                afr[mt][2] = ab[(m + gid)     * PAD_A + k8 + qid + 4];
                afr[mt][3] = ab[(m + 8 + gid) * PAD_A + k8 + qid + 4];
            }
#pragma unroll
            for (int nt = 0; nt < 8; nt++) {
                int n = wn * 64 + nt * 8 + gid;
                uint32_t bfr[2];
                bfr[0] = Bs[buf][(k8 + qid)     * PAD_B + n];
                bfr[1] = Bs[buf][(k8 + qid + 4) * PAD_B + n];
                mma_tf32(acc[0][nt], afr[0], bfr);
                mma_tf32(acc[1][nt], afr[1], bfr);
            }
        }

        if (tile + 1 < nTiles) {
            int nb = buf ^ 1;
            uint32_t* as = &As[nb][a_r * PAD_A + a_k];
            as[0] = f2tf32(av0.x); as[1] = f2tf32(av0.y);
            as[2] = f2tf32(av0.z); as[3] = f2tf32(av0.w);
            as[4] = f2tf32(av1.x); as[5] = f2tf32(av1.y);
            as[6] = f2tf32(av1.z); as[7] = f2tf32(av1.w);
            uint32_t* bs = &Bs[nb][b_k * PAD_B + b_c];
            bs[0] = f2tf32(bv0.x); bs[1] = f2tf32(bv0.y);
            bs[2] = f2tf32(bv0.z); bs[3] = f2tf32(bv0.w);
            bs[4] = f2tf32(bv1.x); bs[5] = f2tf32(bv1.y);
            bs[6] = f2tf32(bv1.z); bs[7] = f2tf32(bv1.w);
            __syncthreads();
            buf = nb;
        }
    }

    // ---- epilogue ----
#pragma unroll
    for (int mt = 0; mt < 2; mt++) {
        int r_lo = row0 + wm * 32 + mt * 16 + gid;
        int r_hi = r_lo + 8;
        bool z_lo = (rowmask != nullptr) && (rowmask[r_lo] != 0);
        bool z_hi = (rowmask != nullptr) && (rowmask[r_hi] != 0);
#pragma unroll
        for (int nt = 0; nt < 8; nt++) {
            int col = col0 + wn * 64 + nt * 8 + qid * 2;
            float b0 = bias[col], b1 = bias[col + 1];
            float2 vlo, vhi;
            vlo.x = acc[mt][nt][0] + b0;
            vlo.y = acc[mt][nt][1] + b1;
            vhi.x = acc[mt][nt][2] + b0;
            vhi.y = acc[mt][nt][3] + b1;
            if (RELU) {
                vlo.x = fmaxf(vlo.x, 0.f); vlo.y = fmaxf(vlo.y, 0.f);
                vhi.x = fmaxf(vhi.x, 0.f); vhi.y = fmaxf(vhi.y, 0.f);
            }
            if (z_lo) { vlo.x = 0.f; vlo.y = 0.f; }
            if (z_hi) { vhi.x = 0.f; vhi.y = 0.f; }
            *reinterpret_cast<float2*>(&C[(size_t)r_lo * N + col]) = vlo;
            *reinterpret_cast<float2*>(&C[(size_t)r_hi * N + col]) = vhi;
        }
    }
}

// ============================================================================
// Deformable sampling: one block (256 threads) per query.
// Reads fused projection buffer g_oa: row = [offs(256) | aw(128)], stride 384.
// ============================================================================
__global__ void sample_kernel(const float* __restrict__ g_oa,
                              const float* __restrict__ g_value,
                              const float* __restrict__ refpts,
                              float* __restrict__ g_out,
                              int Lq, int Lin)
{
    const int q = blockIdx.x;
    const int n = q / Lq;
    const int t = threadIdx.x;

    __shared__ float s_locx[128];
    __shared__ float s_locy[128];
    __shared__ float s_w[128];

    if (t < 128) {
        const int l = (t >> 2) & 3;
        float a = g_oa[(size_t)q * 384 + 256 + t];
        float m = a;
#pragma unroll
        for (int o = 8; o > 0; o >>= 1)
            m = fmaxf(m, __shfl_xor_sync(0xffffffffu, m, o));
        float e = expf(a - m);
        float s = e;
#pragma unroll
        for (int o = 8; o > 0; o >>= 1)
            s += __shfl_xor_sync(0xffffffffu, s, o);
        s_w[t] = e / s;

        const float invWH[4] = {1.f / 128.f, 1.f / 64.f, 1.f / 32.f, 1.f / 16.f};
        float ox = g_oa[(size_t)q * 384 + 2 * t + 0];
        float oy = g_oa[(size_t)q * 384 + 2 * t + 1];
        float rx = refpts[((size_t)q * 4 + l) * 2 + 0];
        float ry = refpts[((size_t)q * 4 + l) * 2 + 1];
        s_locx[t] = rx + ox * invWH[l];
        s_locy[t] = ry + oy * invWH[l];
    }
    __syncthreads();

    const int h = t >> 5;
    const int d = t & 31;

    const int HW[4] = {128, 64, 32, 16};
    const int ST[4] = {0, 16384, 20480, 21504};

    float acc = 0.f;
#pragma unroll
    for (int l = 0; l < NLVL; l++) {
        const int   W  = HW[l];
        const float Wf = (float)W;
        const float* vbase =
            g_value + ((size_t)n * Lin + ST[l]) * D_MODEL + h * HDIM + d;
#pragma unroll
        for (int p = 0; p < NPTS; p++) {
            const int pi = h * 16 + l * 4 + p;
            const float w = s_w[pi];
            const float x = s_locx[pi] * Wf - 0.5f;
            const float y = s_locy[pi] * Wf - 0.5f;
            const float x0 = floorf(x), y0 = floorf(y);
            const float dx = x - x0,   dy = y - y0;
            const float wx[2] = {1.f - dx, dx};
            const float wy[2] = {1.f - dy, dy};
            float samp = 0.f;
#pragma unroll
            for (int cy = 0; cy < 2; cy++) {
#pragma unroll
                for (int cx = 0; cx < 2; cx++) {
                    float fx = x0 + (float)cx;
                    float fy = y0 + (float)cy;
                    if (fx >= 0.f && fx <= Wf - 1.f &&
                        fy >= 0.f && fy <= Wf - 1.f) {
                        int ix = (int)fx;
                        int iy = (int)fy;
                        samp += wx[cx] * wy[cy] *
                                __ldg(&vbase[(size_t)(iy * W + ix) * D_MODEL]);
                    }
                }
            }
            acc += w * samp;
        }
    }
    g_out[(size_t)q * D_MODEL + t] = acc;
}

// ============================================================================
// Fused residual-add + LayerNorm over last dim (256). One warp per row.
// ============================================================================
__global__ void add_ln_kernel(const float* __restrict__ a,
                              const float* __restrict__ b,
                              const float* __restrict__ gamma,
                              const float* __restrict__ beta,
                              float* __restrict__ out, int rows)
{
    const int row  = blockIdx.x * blockDim.y + threadIdx.y;
    if (row >= rows) return;
    const int lane = threadIdx.x;

    const float* pa = a + (size_t)row * D_MODEL;
    const float* pb = b + (size_t)row * D_MODEL;

    float v[8];
    float s = 0.f, s2 = 0.f;
#pragma unroll
    for (int i = 0; i < 8; i++) {
        int c = lane + 32 * i;
        float x = pa[c] + pb[c];
        v[i] = x;
        s  += x;
        s2 += x * x;
    }
#pragma unroll
    for (int o = 16; o > 0; o >>= 1) {
        s  += __shfl_xor_sync(0xffffffffu, s,  o);
        s2 += __shfl_xor_sync(0xffffffffu, s2, o);
    }
    const float mean = s * (1.f / 256.f);
    const float var  = s2 * (1.f / 256.f) - mean * mean;
    const float inv  = rsqrtf(var + 1e-5f);

    float* po = out + (size_t)row * D_MODEL;
#pragma unroll
    for (int i = 0; i < 8; i++) {
        int c = lane + 32 * i;
        po[c] = (v[i] - mean) * inv * gamma[c] + beta[c];
    }
}

// ============================================================================
// Launch
// ============================================================================
extern "C" void kernel_launch(void* const* d_in, const int* in_sizes, int n_in,
                              void* d_out, int out_size)
{
    const float* tgt    = (const float*)d_in[0];
    const float* qpos   = (const float*)d_in[1];
    const float* refpts = (const float*)d_in[2];
    const float* src    = (const float*)d_in[3];
    const unsigned char* mask = (const unsigned char*)d_in[6];
    const float* W_off  = (const float*)d_in[7];
    const float* b_off  = (const float*)d_in[8];
    const float* W_attn = (const float*)d_in[9];
    const float* b_attn = (const float*)d_in[10];
    const float* W_val  = (const float*)d_in[11];
    const float* b_val  = (const float*)d_in[12];
    const float* W_out  = (const float*)d_in[13];
    const float* b_out  = (const float*)d_in[14];
    const float* ln1_g  = (const float*)d_in[15];
    const float* ln1_b  = (const float*)d_in[16];
    const float* W_fc1  = (const float*)d_in[17];
    const float* b_fc1  = (const float*)d_in[18];
    const float* W_fc2  = (const float*)d_in[19];
    const float* b_fc2  = (const float*)d_in[20];
    const float* ln2_g  = (const float*)d_in[21];
    const float* ln2_b  = (const float*)d_in[22];
    float* out = (float*)d_out;

    const int NLq  = in_sizes[0] / D_MODEL;   // 32768
    const int NLin = in_sizes[3] / D_MODEL;   // 87040
    const int Nb   = NLin / LIN_TOT;          // 4
    const int Lq   = NLq / Nb;                // 8192

    void* sp = nullptr;
    cudaGetSymbolAddress(&sp, g_scratch);
    float* S       = (float*)sp;
    float* g_value = S + OFF_VALUE;
    float* g_oa    = S + OFF_OA;
    float* g_samp  = S + OFF_SAMP;
    float* g_attn  = S + OFF_ATTN;
    float* g_x     = S + OFF_X;
    float* g_h     = S + OFF_H;
    float* g_ff    = S + OFF_FF;
    float* g_Wc    = S + OFF_WCAT;
    float* g_bc    = S + OFF_BCAT;

    // 0. concat [W_off|W_attn] weights (tiny)
    concat_w_kernel<<<(256 * 384 + 255) / 256, 256>>>(
        W_off, b_off, W_attn, b_attn, g_Wc, g_bc);

    // 1. value = src @ W_val + b_val, masked rows zeroed
    gemm_tf32_kernel<false><<<dim3(D_MODEL / 128, NLin / 128), 256>>>(
        src, nullptr, W_val, b_val, mask, g_value, NLin, D_MODEL, D_MODEL);

    // 2. fused offsets+logits: (tgt + query_pos) @ [W_off|W_attn] -> [NLq, 384]
    //    (residual add fused into the A-load path)
    gemm_tf32_kernel<false><<<dim3(384 / 128, NLq / 128), 256>>>(
        tgt, qpos, g_Wc, g_bc, nullptr, g_oa, NLq, 384, D_MODEL);

    // 3. softmax + deformable bilinear sampling -> g_samp [NLq, 256]
    sample_kernel<<<NLq, 256>>>(g_oa, g_value, refpts, g_samp, Lq, LIN_TOT);

    // 4. attn_out = samp @ W_out + b_out
    gemm_tf32_kernel<false><<<dim3(D_MODEL / 128, NLq / 128), 256>>>(
        g_samp, nullptr, W_out, b_out, nullptr, g_attn, NLq, D_MODEL, D_MODEL);

    // 5. x = LN(tgt + attn_out)
    add_ln_kernel<<<NLq / 8, dim3(32, 8)>>>(tgt, g_attn, ln1_g, ln1_b, g_x, NLq);

    // 6. h = relu(x @ W_fc1 + b_fc1)
    gemm_tf32_kernel<true><<<dim3(DFF / 128, NLq / 128), 256>>>(
        g_x, nullptr, W_fc1, b_fc1, nullptr, g_h, NLq, DFF, D_MODEL);

    // 7. ff = h @ W_fc2 + b_fc2
    gemm_tf32_kernel<false><<<dim3(D_MODEL / 128, NLq / 128), 256>>>(
        g_h, nullptr, W_fc2, b_fc2, nullptr, g_ff, NLq, D_MODEL, DFF);

    // 8. out = LN(x + ff)
    add_ln_kernel<<<NLq / 8, dim3(32, 8)>>>(g_x, g_ff, ln2_g, ln2_b, out, NLq);
}